// round 10
// baseline (speedup 1.0000x reference)
#include <cuda_runtime.h>
#include <cuda_bf16.h>
#include <cstdint>

#define BATCH  4
#define SEQ    4096
#define DMODEL 1024
#define HD     64
#define BT     (BATCH * SEQ)
#define NSPLIT 4
#define SPLEN  (SEQ / NSPLIT)
#define LOG2E  1.4426950408889634f

// Scratch (alloc-free rule: __device__ globals).
// g_Q: raw rows, pre-scaled by 0.125*log2(e), tf32 bits.
// g_K: rows with columns permuted within 8-groups (c -> ((c&3)<<1)|((c&4)>>2)).
// g_V: V TRANSPOSED: [b][n=HD][s=SEQ], s permuted within 8-groups likewise.
__device__ float g_Q[BT * HD];
__device__ float g_K[BT * HD];
__device__ float g_V[BT * HD];
__device__ float g_O4[NSPLIT * BT * HD];
__device__ float g_M4[NSPLIT * BT];
__device__ float g_L4[NSPLIT * BT];

__device__ __forceinline__ uint32_t f2tf32(float f) {
    uint32_t u;
    asm("cvt.rna.tf32.f32 %0, %1;" : "=r"(u) : "f"(f));
    return u;
}

__device__ __forceinline__ void mma_tf32(float c[4],
                                         uint32_t a0, uint32_t a1, uint32_t a2, uint32_t a3,
                                         uint32_t b0, uint32_t b1) {
    asm volatile(
        "mma.sync.aligned.m16n8k8.row.col.f32.tf32.tf32.f32 "
        "{%0,%1,%2,%3}, {%4,%5,%6,%7}, {%8,%9}, {%0,%1,%2,%3};"
        : "+f"(c[0]), "+f"(c[1]), "+f"(c[2]), "+f"(c[3])
        : "r"(a0), "r"(a1), "r"(a2), "r"(a3), "r"(b0), "r"(b1));
}

__device__ __forceinline__ void cp_async16(uint32_t smem_addr, const void* gmem) {
    asm volatile("cp.async.cg.shared.global [%0], [%1], 16;"
                 :: "r"(smem_addr), "l"(gmem) : "memory");
}
__device__ __forceinline__ void cp_commit() {
    asm volatile("cp.async.commit_group;" ::: "memory");
}
template <int N>
__device__ __forceinline__ void cp_wait() {
    asm volatile("cp.async.wait_group %0;" :: "n"(N) : "memory");
}

// ---------------------------------------------------------------------------
// Projection (tensor cores, M=128 tile, warp owns 32 rows; register-staged
// prefetch). Epilogues write the attn-friendly layouts described above.
// ---------------------------------------------------------------------------
#define PXS 36

__global__ __launch_bounds__(128, 3) void proj_kernel(
    const float* __restrict__ x,
    const float* __restrict__ wq,
    const float* __restrict__ wk,
    const float* __restrict__ wv)
{
    __shared__ uint32_t sX[128 * PXS];
    __shared__ uint32_t sW[64 * PXS];

    const int tid  = threadIdx.x;
    const int warp = tid >> 5;
    const int lane = tid & 31;
    const int gid  = lane >> 2;
    const int tig  = lane & 3;
    const int row0 = blockIdx.x * 128;
    const int o    = blockIdx.y;
    const int mr0  = 32 * warp + gid;
    const int mr1  = mr0 + 16;

    const float* w = (o == 0) ? wq : (o == 1) ? wk : wv;

    float acc[2][8][4] = {};

    float4 xr[8], wr[4];
    #pragma unroll
    for (int it = 0; it < 8; ++it) {
        int idx = tid + it * 128;
        int m  = idx >> 3;
        int c4 = idx & 7;
        xr[it] = *(const float4*)&x[(size_t)(row0 + m) * DMODEL + 4 * c4];
    }
    #pragma unroll
    for (int it = 0; it < 4; ++it) {
        int idx = tid + it * 128;
        int m  = idx >> 3;
        int c4 = idx & 7;
        wr[it] = *(const float4*)&w[(size_t)m * DMODEL + 4 * c4];
    }

    for (int k0 = 0; k0 < DMODEL; k0 += 32) {
        #pragma unroll
        for (int it = 0; it < 8; ++it) {
            int idx = tid + it * 128;
            int m  = idx >> 3;
            int c4 = idx & 7;
            uint4 u;
            u.x = f2tf32(xr[it].x); u.y = f2tf32(xr[it].y);
            u.z = f2tf32(xr[it].z); u.w = f2tf32(xr[it].w);
            *(uint4*)&sX[m * PXS + 4 * c4] = u;
        }
        #pragma unroll
        for (int it = 0; it < 4; ++it) {
            int idx = tid + it * 128;
            int m  = idx >> 3;
            int c4 = idx & 7;
            uint4 uw;
            uw.x = f2tf32(wr[it].x); uw.y = f2tf32(wr[it].y);
            uw.z = f2tf32(wr[it].z); uw.w = f2tf32(wr[it].w);
            *(uint4*)&sW[m * PXS + 4 * c4] = uw;
        }
        __syncthreads();

        if (k0 + 32 < DMODEL) {
            #pragma unroll
            for (int it = 0; it < 8; ++it) {
                int idx = tid + it * 128;
                int m  = idx >> 3;
                int c4 = idx & 7;
                xr[it] = *(const float4*)&x[(size_t)(row0 + m) * DMODEL + k0 + 32 + 4 * c4];
            }
            #pragma unroll
            for (int it = 0; it < 4; ++it) {
                int idx = tid + it * 128;
                int m  = idx >> 3;
                int c4 = idx & 7;
                wr[it] = *(const float4*)&w[(size_t)m * DMODEL + k0 + 32 + 4 * c4];
            }
        }

        #pragma unroll
        for (int ks = 0; ks < 4; ++ks) {
            uint32_t p0 = sX[(mr0)      * PXS + 8 * ks + tig];
            uint32_t p1 = sX[(mr0 + 8)  * PXS + 8 * ks + tig];
            uint32_t p2 = sX[(mr0)      * PXS + 8 * ks + tig + 4];
            uint32_t p3 = sX[(mr0 + 8)  * PXS + 8 * ks + tig + 4];
            uint32_t q0 = sX[(mr1)      * PXS + 8 * ks + tig];
            uint32_t q1 = sX[(mr1 + 8)  * PXS + 8 * ks + tig];
            uint32_t q2 = sX[(mr1)      * PXS + 8 * ks + tig + 4];
            uint32_t q3 = sX[(mr1 + 8)  * PXS + 8 * ks + tig + 4];
            #pragma unroll
            for (int nc = 0; nc < 8; ++nc) {
                uint32_t b0 = sW[(8 * nc + gid) * PXS + 8 * ks + tig];
                uint32_t b1 = sW[(8 * nc + gid) * PXS + 8 * ks + tig + 4];
                mma_tf32(acc[0][nc], p0, p1, p2, p3, b0, b1);
                mma_tf32(acc[1][nc], q0, q1, q2, q3, b0, b1);
            }
        }
        __syncthreads();
    }

    // col permutation within 8-group: c -> ((c&3)<<1)|((c&4)>>2)
    const int c0 = 2 * tig;            // fragment col (within 8-group)
    const int pc0 = ((c0 & 3) << 1) | ((c0 & 4) >> 2);
    const int pc1 = (((c0 + 1) & 3) << 1) | (((c0 + 1) & 4) >> 2);
    const int pgid = ((gid & 3) << 1) | ((gid & 4) >> 2);

    #pragma unroll
    for (int r = 0; r < 2; ++r) {
        const int mra = (r == 0) ? mr0 : mr1;
        #pragma unroll
        for (int half = 0; half < 2; ++half) {
            const int mr = mra + 8 * half;
            const int t  = row0 + mr;              // global token
            if (o == 0) {
                // Q: raw rows, pre-scaled by 0.125*log2e
                #pragma unroll
                for (int nc = 0; nc < 8; ++nc) {
                    float v0 = acc[r][nc][2 * half + 0] * (0.125f * LOG2E);
                    float v1 = acc[r][nc][2 * half + 1] * (0.125f * LOG2E);
                    *(float2*)&g_Q[(size_t)t * HD + 8 * nc + 2 * tig] =
                        make_float2(__uint_as_float(f2tf32(v0)),
                                    __uint_as_float(f2tf32(v1)));
                }
            } else if (o == 1) {
                // K: rows with permuted cols
                #pragma unroll
                for (int nc = 0; nc < 8; ++nc) {
                    g_K[(size_t)t * HD + 8 * nc + pc0] =
                        __uint_as_float(f2tf32(acc[r][nc][2 * half + 0]));
                    g_K[(size_t)t * HD + 8 * nc + pc1] =
                        __uint_as_float(f2tf32(acc[r][nc][2 * half + 1]));
                }
            } else {
                // V transposed: g_V[b*HD*SEQ + n*SEQ + s'], s' group-permuted.
                const int b  = t >> 12;            // t / SEQ
                const int s  = t & (SEQ - 1);
                const int sp = (s & ~7) | pgid;    // s&7 == gid always here
                float* base = g_V + (size_t)b * HD * SEQ + sp;
                #pragma unroll
                for (int nc = 0; nc < 8; ++nc) {
                    base[(size_t)(8 * nc + 2 * tig)     * SEQ] =
                        __uint_as_float(f2tf32(acc[r][nc][2 * half + 0]));
                    base[(size_t)(8 * nc + 2 * tig + 1) * SEQ] =
                        __uint_as_float(f2tf32(acc[r][nc][2 * half + 1]));
                }
            }
        }
    }
}

// ---------------------------------------------------------------------------
// Flash attention, split-KV x4, cp.async-pipelined. Softmax in exp2 domain.
// K and V^T tiles share the same fragment layout: B-frag pair = one
// conflict-free LDS.64 (stride 72 => banks 8*gid+2*tig, all distinct).
// ---------------------------------------------------------------------------
#define BM 64
#define BN 64
#define SKP 72
#define SVP 72
#define NITER (SPLEN / BN)

__global__ __launch_bounds__(128, 3) void attn_kernel()
{
    __shared__ uint32_t sK[BM * SKP];   // Q (prologue) then K tiles
    __shared__ uint32_t sV[64 * SVP];   // V^T tiles [n=64][s=64 permuted]

    const int tid  = threadIdx.x;
    const int warp = tid >> 5;
    const int lane = tid & 31;
    const int gid  = lane >> 2;
    const int tig  = lane & 3;
    const int b    = blockIdx.y;
    const int t0   = blockIdx.x * BM;
    const int split = blockIdx.z;
    const int mrow = 16 * warp + gid;
    const int sbeg = split * SPLEN;

    const uint32_t sK_base = (uint32_t)__cvta_generic_to_shared(sK);
    const uint32_t sV_base = (uint32_t)__cvta_generic_to_shared(sV);
    const float* VT = g_V + (size_t)b * HD * SEQ;   // [n][s]

    // ---- Load Q (scaled + tf32 bits) ----
    const float* Qg = g_Q + ((size_t)b * SEQ + t0) * HD;
    #pragma unroll
    for (int it = 0; it < 8; ++it) {
        int idx = tid + it * 128;
        int r  = idx >> 4;
        int c4 = idx & 15;
        *(float4*)&sK[r * SKP + 4 * c4] = *(const float4*)&Qg[(size_t)r * HD + 4 * c4];
    }
    __syncthreads();

    uint32_t Aq[8][4];
    #pragma unroll
    for (int k = 0; k < 8; ++k) {
        Aq[k][0] = sK[(mrow)     * SKP + 8 * k + tig];
        Aq[k][1] = sK[(mrow + 8) * SKP + 8 * k + tig];
        Aq[k][2] = sK[(mrow)     * SKP + 8 * k + tig + 4];
        Aq[k][3] = sK[(mrow + 8) * SKP + 8 * k + tig + 4];
    }
    __syncthreads();

    // ---- Prologue: issue K0 (group), then V0 (group) ----
    {
        const float* Kg = g_K + ((size_t)b * SEQ + sbeg) * HD;
        #pragma unroll
        for (int it = 0; it < 8; ++it) {
            int idx = tid + it * 128;
            int r  = idx >> 4;
            int c4 = idx & 15;
            cp_async16(sK_base + (r * SKP + 4 * c4) * 4, &Kg[(size_t)r * HD + 4 * c4]);
        }
        cp_commit();
        #pragma unroll
        for (int it = 0; it < 8; ++it) {
            int idx = tid + it * 128;
            int r  = idx >> 4;           // n row
            int c4 = idx & 15;           // s-col chunk
            cp_async16(sV_base + (r * SVP + 4 * c4) * 4,
                       &VT[(size_t)r * SEQ + sbeg + 4 * c4]);
        }
        cp_commit();
    }

    float O[8][4] = {};
    float m0 = -1e30f, m1 = -1e30f, l0 = 0.f, l1 = 0.f;

    const int src0 = (lane & 28) | (tig >> 1);
    const int src2 = src0 | 2;
    const bool odd = (tig & 1);

    for (int i = 0; i < NITER; ++i) {
        cp_wait<1>();
        __syncthreads();

        // ---- S = Q @ K^T (B-frag pair = one LDS.64, conflict-free) ----
        float sacc[8][4] = {};
        #pragma unroll
        for (int k = 0; k < 8; ++k) {
            #pragma unroll
            for (int nc = 0; nc < 8; ++nc) {
                uint2 bb = *(const uint2*)&sK[(8 * nc + gid) * SKP + 8 * k + 2 * tig];
                mma_tf32(sacc[nc], Aq[k][0], Aq[k][1], Aq[k][2], Aq[k][3], bb.x, bb.y);
            }
        }
        __syncthreads();

        if (i + 1 < NITER) {
            const float* Kg = g_K + ((size_t)b * SEQ + sbeg + (i + 1) * BN) * HD;
            #pragma unroll
            for (int it = 0; it < 8; ++it) {
                int idx = tid + it * 128;
                int r  = idx >> 4;
                int c4 = idx & 15;
                cp_async16(sK_base + (r * SKP + 4 * c4) * 4, &Kg[(size_t)r * HD + 4 * c4]);
            }
            cp_commit();
        }

        // ---- Online softmax in exp2 domain ----
        float mx0 = -1e30f, mx1 = -1e30f;
        #pragma unroll
        for (int nc = 0; nc < 8; ++nc) {
            mx0 = fmaxf(mx0, fmaxf(sacc[nc][0], sacc[nc][1]));
            mx1 = fmaxf(mx1, fmaxf(sacc[nc][2], sacc[nc][3]));
        }
        mx0 = fmaxf(mx0, __shfl_xor_sync(0xffffffffu, mx0, 1));
        mx0 = fmaxf(mx0, __shfl_xor_sync(0xffffffffu, mx0, 2));
        mx1 = fmaxf(mx1, __shfl_xor_sync(0xffffffffu, mx1, 1));
        mx1 = fmaxf(mx1, __shfl_xor_sync(0xffffffffu, mx1, 2));

        float mn0 = fmaxf(m0, mx0), mn1 = fmaxf(m1, mx1);
        float al0 = exp2f(m0 - mn0), al1 = exp2f(m1 - mn1);

        float sum0 = 0.f, sum1 = 0.f;
        #pragma unroll
        for (int nc = 0; nc < 8; ++nc) {
            sacc[nc][0] = exp2f(sacc[nc][0] - mn0);
            sacc[nc][1] = exp2f(sacc[nc][1] - mn0);
            sacc[nc][2] = exp2f(sacc[nc][2] - mn1);
            sacc[nc][3] = exp2f(sacc[nc][3] - mn1);
            sum0 += sacc[nc][0] + sacc[nc][1];
            sum1 += sacc[nc][2] + sacc[nc][3];
        }
        sum0 += __shfl_xor_sync(0xffffffffu, sum0, 1);
        sum0 += __shfl_xor_sync(0xffffffffu, sum0, 2);
        sum1 += __shfl_xor_sync(0xffffffffu, sum1, 1);
        sum1 += __shfl_xor_sync(0xffffffffu, sum1, 2);

        l0 = l0 * al0 + sum0;  m0 = mn0;
        l1 = l1 * al1 + sum1;  m1 = mn1;

        #pragma unroll
        for (int nc = 0; nc < 8; ++nc) {
            O[nc][0] *= al0; O[nc][1] *= al0;
            O[nc][2] *= al1; O[nc][3] *= al1;
        }

        #pragma unroll
        for (int nc = 0; nc < 8; ++nc)
            #pragma unroll
            for (int j = 0; j < 4; ++j)
                sacc[nc][j] = __uint_as_float(f2tf32(sacc[nc][j]));

        if (i + 1 < NITER) cp_wait<1>(); else cp_wait<0>();
        __syncthreads();

        // ---- O += P @ V (V^T tile: same LDS.64 fragment path) ----
        #pragma unroll
        for (int ks = 0; ks < 8; ++ks) {
            float x0 = __shfl_sync(0xffffffffu, sacc[ks][0], src0);
            float x1 = __shfl_sync(0xffffffffu, sacc[ks][1], src0);
            float x2 = __shfl_sync(0xffffffffu, sacc[ks][2], src0);
            float x3 = __shfl_sync(0xffffffffu, sacc[ks][3], src0);
            float y0 = __shfl_sync(0xffffffffu, sacc[ks][0], src2);
            float y1 = __shfl_sync(0xffffffffu, sacc[ks][1], src2);
            float y2 = __shfl_sync(0xffffffffu, sacc[ks][2], src2);
            float y3 = __shfl_sync(0xffffffffu, sacc[ks][3], src2);
            uint32_t a0 = __float_as_uint(odd ? x1 : x0);
            uint32_t a1 = __float_as_uint(odd ? x3 : x2);
            uint32_t a2 = __float_as_uint(odd ? y1 : y0);
            uint32_t a3 = __float_as_uint(odd ? y3 : y2);
            #pragma unroll
            for (int nc = 0; nc < 8; ++nc) {
                uint2 bb = *(const uint2*)&sV[(8 * nc + gid) * SVP + 8 * ks + 2 * tig];
                mma_tf32(O[nc], a0, a1, a2, a3, bb.x, bb.y);
            }
        }
        __syncthreads();

        if (i + 1 < NITER) {
            #pragma unroll
            for (int it = 0; it < 8; ++it) {
                int idx = tid + it * 128;
                int r  = idx >> 4;
                int c4 = idx & 15;
                cp_async16(sV_base + (r * SVP + 4 * c4) * 4,
                           &VT[(size_t)r * SEQ + sbeg + (i + 1) * BN + 4 * c4]);
            }
            cp_commit();
        }
    }

    // ---- Write unnormalized partials + stats ----
    const size_t row0g = (size_t)b * SEQ + t0;
    float* Op = g_O4 + (size_t)split * BT * HD;
    #pragma unroll
    for (int nc = 0; nc < 8; ++nc) {
        int c = 8 * nc + 2 * tig;
        float* p0 = &Op[(row0g + mrow)     * HD + c];
        float* p1 = &Op[(row0g + mrow + 8) * HD + c];
        *(float2*)p0 = make_float2(O[nc][0], O[nc][1]);
        *(float2*)p1 = make_float2(O[nc][2], O[nc][3]);
    }
    if (tig == 0) {
        g_M4[split * BT + row0g + mrow]     = m0;
        g_M4[split * BT + row0g + mrow + 8] = m1;
        g_L4[split * BT + row0g + mrow]     = l0;
        g_L4[split * BT + row0g + mrow + 8] = l1;
    }
}

// ---------------------------------------------------------------------------
// Combine splits (exp2 domain): O = sum_s w_s O_s / sum_s w_s l_s.
// ---------------------------------------------------------------------------
__global__ __launch_bounds__(256) void combine_kernel(float* __restrict__ out)
{
    int idx = blockIdx.x * 256 + threadIdx.x;
    int row = idx >> 4;

    float m[NSPLIT], l[NSPLIT];
    float mstar = -1e30f;
    #pragma unroll
    for (int s = 0; s < NSPLIT; ++s) {
        m[s] = g_M4[s * BT + row];
        l[s] = g_L4[s * BT + row];
        mstar = fmaxf(mstar, m[s]);
    }
    float den = 0.f;
    float4 num = make_float4(0.f, 0.f, 0.f, 0.f);
    #pragma unroll
    for (int s = 0; s < NSPLIT; ++s) {
        float wgt = exp2f(m[s] - mstar);
        den += wgt * l[s];
        float4 o = *(const float4*)&g_O4[(size_t)s * BT * HD + (size_t)idx * 4];
        num.x += wgt * o.x; num.y += wgt * o.y;
        num.z += wgt * o.z; num.w += wgt * o.w;
    }
    float inv = 1.0f / den;
    num.x *= inv; num.y *= inv; num.z *= inv; num.w *= inv;
    *(float4*)&out[(size_t)idx * 4] = num;
}

extern "C" void kernel_launch(void* const* d_in, const int* in_sizes, int n_in,
                              void* d_out, int out_size)
{
    const float* x  = (const float*)d_in[0];
    const float* wq = (const float*)d_in[1];
    const float* wk = (const float*)d_in[2];
    const float* wv = (const float*)d_in[3];
    float* out = (float*)d_out;

    dim3 gridP(BT / 128, 3);
    proj_kernel<<<gridP, 128>>>(x, wq, wk, wv);

    dim3 gridA(SEQ / BM, BATCH, NSPLIT);
    attn_kernel<<<gridA, 128>>>();

    combine_kernel<<<BT * HD / 4 / 256, 256>>>(out);
}

// round 11
// speedup vs baseline: 1.4648x; 1.4648x over previous
#include <cuda_runtime.h>
#include <cuda_bf16.h>
#include <cstdint>

#define BATCH  4
#define SEQ    4096
#define DMODEL 1024
#define HD     64
#define BT     (BATCH * SEQ)
#define NSPLIT 4
#define SPLEN  (SEQ / NSPLIT)
#define LOG2E  1.4426950408889634f

// Scratch (alloc-free rule: __device__ globals). Q/K/V hold tf32-rounded bits.
// Q rows are pre-scaled by 0.125*log2(e)  (exp2-domain softmax).
__device__ float g_Q[BT * HD];
__device__ float g_K[BT * HD];
__device__ float g_V[BT * HD];
__device__ float g_O4[NSPLIT * BT * HD];
__device__ float g_M4[NSPLIT * BT];
__device__ float g_L4[NSPLIT * BT];

__device__ __forceinline__ uint32_t f2tf32(float f) {
    uint32_t u;
    asm("cvt.rna.tf32.f32 %0, %1;" : "=r"(u) : "f"(f));
    return u;
}

__device__ __forceinline__ float ex2(float x) {
    float r;
    asm("ex2.approx.f32 %0, %1;" : "=f"(r) : "f"(x));
    return r;
}

__device__ __forceinline__ void mma_tf32(float c[4],
                                         uint32_t a0, uint32_t a1, uint32_t a2, uint32_t a3,
                                         uint32_t b0, uint32_t b1) {
    asm volatile(
        "mma.sync.aligned.m16n8k8.row.col.f32.tf32.tf32.f32 "
        "{%0,%1,%2,%3}, {%4,%5,%6,%7}, {%8,%9}, {%0,%1,%2,%3};"
        : "+f"(c[0]), "+f"(c[1]), "+f"(c[2]), "+f"(c[3])
        : "r"(a0), "r"(a1), "r"(a2), "r"(a3), "r"(b0), "r"(b1));
}

__device__ __forceinline__ void cp_async16(uint32_t smem_addr, const void* gmem) {
    asm volatile("cp.async.cg.shared.global [%0], [%1], 16;"
                 :: "r"(smem_addr), "l"(gmem) : "memory");
}
__device__ __forceinline__ void cp_commit() {
    asm volatile("cp.async.commit_group;" ::: "memory");
}
template <int N>
__device__ __forceinline__ void cp_wait() {
    asm volatile("cp.async.wait_group %0;" :: "n"(N) : "memory");
}

// ---------------------------------------------------------------------------
// Projection on tensor cores. Block tile M=128 x N=64; warp owns 32 rows
// (B-frags amortized over two row-set mmas). Register-staged prefetch.
// Coalesced float2 epilogue; Q pre-scaled by 0.125*log2e.
// ---------------------------------------------------------------------------
#define PXS 36

__global__ __launch_bounds__(128, 3) void proj_kernel(
    const float* __restrict__ x,
    const float* __restrict__ wq,
    const float* __restrict__ wk,
    const float* __restrict__ wv)
{
    __shared__ uint32_t sX[128 * PXS];
    __shared__ uint32_t sW[64 * PXS];

    const int tid  = threadIdx.x;
    const int warp = tid >> 5;
    const int lane = tid & 31;
    const int gid  = lane >> 2;
    const int tig  = lane & 3;
    const int row0 = blockIdx.x * 128;
    const int o    = blockIdx.y;
    const int mr0  = 32 * warp + gid;
    const int mr1  = mr0 + 16;

    const float* w = (o == 0) ? wq : (o == 1) ? wk : wv;
    float* outp    = (o == 0) ? g_Q : (o == 1) ? g_K : g_V;
    const float oscale = (o == 0) ? 0.125f * LOG2E : 1.0f;

    float acc[2][8][4] = {};

    float4 xr[8], wr[4];
    #pragma unroll
    for (int it = 0; it < 8; ++it) {
        int idx = tid + it * 128;
        int m  = idx >> 3;
        int c4 = idx & 7;
        xr[it] = *(const float4*)&x[(size_t)(row0 + m) * DMODEL + 4 * c4];
    }
    #pragma unroll
    for (int it = 0; it < 4; ++it) {
        int idx = tid + it * 128;
        int m  = idx >> 3;
        int c4 = idx & 7;
        wr[it] = *(const float4*)&w[(size_t)m * DMODEL + 4 * c4];
    }

    for (int k0 = 0; k0 < DMODEL; k0 += 32) {
        #pragma unroll
        for (int it = 0; it < 8; ++it) {
            int idx = tid + it * 128;
            int m  = idx >> 3;
            int c4 = idx & 7;
            uint4 u;
            u.x = f2tf32(xr[it].x); u.y = f2tf32(xr[it].y);
            u.z = f2tf32(xr[it].z); u.w = f2tf32(xr[it].w);
            *(uint4*)&sX[m * PXS + 4 * c4] = u;
        }
        #pragma unroll
        for (int it = 0; it < 4; ++it) {
            int idx = tid + it * 128;
            int m  = idx >> 3;
            int c4 = idx & 7;
            uint4 uw;
            uw.x = f2tf32(wr[it].x); uw.y = f2tf32(wr[it].y);
            uw.z = f2tf32(wr[it].z); uw.w = f2tf32(wr[it].w);
            *(uint4*)&sW[m * PXS + 4 * c4] = uw;
        }
        __syncthreads();

        if (k0 + 32 < DMODEL) {
            #pragma unroll
            for (int it = 0; it < 8; ++it) {
                int idx = tid + it * 128;
                int m  = idx >> 3;
                int c4 = idx & 7;
                xr[it] = *(const float4*)&x[(size_t)(row0 + m) * DMODEL + k0 + 32 + 4 * c4];
            }
            #pragma unroll
            for (int it = 0; it < 4; ++it) {
                int idx = tid + it * 128;
                int m  = idx >> 3;
                int c4 = idx & 7;
                wr[it] = *(const float4*)&w[(size_t)m * DMODEL + k0 + 32 + 4 * c4];
            }
        }

        #pragma unroll
        for (int ks = 0; ks < 4; ++ks) {
            uint32_t p0 = sX[(mr0)      * PXS + 8 * ks + tig];
            uint32_t p1 = sX[(mr0 + 8)  * PXS + 8 * ks + tig];
            uint32_t p2 = sX[(mr0)      * PXS + 8 * ks + tig + 4];
            uint32_t p3 = sX[(mr0 + 8)  * PXS + 8 * ks + tig + 4];
            uint32_t q0 = sX[(mr1)      * PXS + 8 * ks + tig];
            uint32_t q1 = sX[(mr1 + 8)  * PXS + 8 * ks + tig];
            uint32_t q2 = sX[(mr1)      * PXS + 8 * ks + tig + 4];
            uint32_t q3 = sX[(mr1 + 8)  * PXS + 8 * ks + tig + 4];
            #pragma unroll
            for (int nc = 0; nc < 8; ++nc) {
                uint32_t b0 = sW[(8 * nc + gid) * PXS + 8 * ks + tig];
                uint32_t b1 = sW[(8 * nc + gid) * PXS + 8 * ks + tig + 4];
                mma_tf32(acc[0][nc], p0, p1, p2, p3, b0, b1);
                mma_tf32(acc[1][nc], q0, q1, q2, q3, b0, b1);
            }
        }
        __syncthreads();
    }

    #pragma unroll
    for (int r = 0; r < 2; ++r) {
        const int mr = (r == 0) ? mr0 : mr1;
        #pragma unroll
        for (int nc = 0; nc < 8; ++nc) {
            float* p0 = &outp[(size_t)(row0 + mr) * HD + 8 * nc + 2 * tig];
            float* p1 = &outp[(size_t)(row0 + mr + 8) * HD + 8 * nc + 2 * tig];
            *(float2*)p0 = make_float2(__uint_as_float(f2tf32(acc[r][nc][0] * oscale)),
                                       __uint_as_float(f2tf32(acc[r][nc][1] * oscale)));
            *(float2*)p1 = make_float2(__uint_as_float(f2tf32(acc[r][nc][2] * oscale)),
                                       __uint_as_float(f2tf32(acc[r][nc][3] * oscale)));
        }
    }
}

// ---------------------------------------------------------------------------
// Flash attention, split-KV x4, cp.async-pipelined K/V (separate groups).
// Softmax in exp2 domain (Q pre-scaled by 0.125*log2e; bare MUFU ex2).
// Layouts identical to round 9: SKP=68 (4*gid+tig conflict-free), SVP=72.
// ---------------------------------------------------------------------------
#define BM 64
#define BN 64
#define SKP 68
#define SVP 72
#define NITER (SPLEN / BN)

__global__ __launch_bounds__(128, 3) void attn_kernel()
{
    __shared__ uint32_t sK[BM * SKP];   // Q (prologue) then K tiles
    __shared__ uint32_t sV[BN * SVP];

    const int tid  = threadIdx.x;
    const int warp = tid >> 5;
    const int lane = tid & 31;
    const int gid  = lane >> 2;
    const int tig  = lane & 3;
    const int b    = blockIdx.y;
    const int t0   = blockIdx.x * BM;
    const int split = blockIdx.z;
    const int mrow = 16 * warp + gid;
    const int sbeg = split * SPLEN;

    const uint32_t sK_base = (uint32_t)__cvta_generic_to_shared(sK);
    const uint32_t sV_base = (uint32_t)__cvta_generic_to_shared(sV);

    // ---- Load Q (scaled + tf32 bits) ----
    const float* Qg = g_Q + ((size_t)b * SEQ + t0) * HD;
    #pragma unroll
    for (int it = 0; it < 8; ++it) {
        int idx = tid + it * 128;
        int r  = idx >> 4;
        int c4 = idx & 15;
        *(float4*)&sK[r * SKP + 4 * c4] = *(const float4*)&Qg[(size_t)r * HD + 4 * c4];
    }
    __syncthreads();

    uint32_t Aq[8][4];
    #pragma unroll
    for (int k = 0; k < 8; ++k) {
        Aq[k][0] = sK[(mrow)     * SKP + 8 * k + tig];
        Aq[k][1] = sK[(mrow + 8) * SKP + 8 * k + tig];
        Aq[k][2] = sK[(mrow)     * SKP + 8 * k + tig + 4];
        Aq[k][3] = sK[(mrow + 8) * SKP + 8 * k + tig + 4];
    }
    __syncthreads();   // all warps hoisted before K0 overwrites sK

    // ---- Prologue: issue K0 (group), then V0 (group) ----
    {
        const float* Kg = g_K + ((size_t)b * SEQ + sbeg) * HD;
        const float* Vg = g_V + ((size_t)b * SEQ + sbeg) * HD;
        #pragma unroll
        for (int it = 0; it < 8; ++it) {
            int idx = tid + it * 128;
            int r  = idx >> 4;
            int c4 = idx & 15;
            cp_async16(sK_base + (r * SKP + 4 * c4) * 4, &Kg[(size_t)r * HD + 4 * c4]);
        }
        cp_commit();
        #pragma unroll
        for (int it = 0; it < 8; ++it) {
            int idx = tid + it * 128;
            int r  = idx >> 4;
            int c4 = idx & 15;
            cp_async16(sV_base + (r * SVP + 4 * c4) * 4, &Vg[(size_t)r * HD + 4 * c4]);
        }
        cp_commit();
    }

    float O[8][4] = {};
    float m0 = -1e30f, m1 = -1e30f, l0 = 0.f, l1 = 0.f;

    const int src0 = (lane & 28) | (tig >> 1);
    const int src2 = src0 | 2;
    const bool odd = (tig & 1);

    for (int i = 0; i < NITER; ++i) {
        cp_wait<1>();
        __syncthreads();

        // ---- S = Q @ K^T ----
        float sacc[8][4] = {};
        #pragma unroll
        for (int k = 0; k < 8; ++k) {
            #pragma unroll
            for (int nc = 0; nc < 8; ++nc) {
                uint32_t b0 = sK[(8 * nc + gid) * SKP + 8 * k + tig];
                uint32_t b1 = sK[(8 * nc + gid) * SKP + 8 * k + tig + 4];
                mma_tf32(sacc[nc], Aq[k][0], Aq[k][1], Aq[k][2], Aq[k][3], b0, b1);
            }
        }
        __syncthreads();

        if (i + 1 < NITER) {
            const float* Kg = g_K + ((size_t)b * SEQ + sbeg + (i + 1) * BN) * HD;
            #pragma unroll
            for (int it = 0; it < 8; ++it) {
                int idx = tid + it * 128;
                int r  = idx >> 4;
                int c4 = idx & 15;
                cp_async16(sK_base + (r * SKP + 4 * c4) * 4, &Kg[(size_t)r * HD + 4 * c4]);
            }
            cp_commit();
        }

        // ---- Online softmax in exp2 domain ----
        float mx0 = -1e30f, mx1 = -1e30f;
        #pragma unroll
        for (int nc = 0; nc < 8; ++nc) {
            mx0 = fmaxf(mx0, fmaxf(sacc[nc][0], sacc[nc][1]));
            mx1 = fmaxf(mx1, fmaxf(sacc[nc][2], sacc[nc][3]));
        }
        mx0 = fmaxf(mx0, __shfl_xor_sync(0xffffffffu, mx0, 1));
        mx0 = fmaxf(mx0, __shfl_xor_sync(0xffffffffu, mx0, 2));
        mx1 = fmaxf(mx1, __shfl_xor_sync(0xffffffffu, mx1, 1));
        mx1 = fmaxf(mx1, __shfl_xor_sync(0xffffffffu, mx1, 2));

        float mn0 = fmaxf(m0, mx0), mn1 = fmaxf(m1, mx1);
        float al0 = ex2(m0 - mn0), al1 = ex2(m1 - mn1);

        float sum0 = 0.f, sum1 = 0.f;
        #pragma unroll
        for (int nc = 0; nc < 8; ++nc) {
            sacc[nc][0] = ex2(sacc[nc][0] - mn0);
            sacc[nc][1] = ex2(sacc[nc][1] - mn0);
            sacc[nc][2] = ex2(sacc[nc][2] - mn1);
            sacc[nc][3] = ex2(sacc[nc][3] - mn1);
            sum0 += sacc[nc][0] + sacc[nc][1];
            sum1 += sacc[nc][2] + sacc[nc][3];
        }
        sum0 += __shfl_xor_sync(0xffffffffu, sum0, 1);
        sum0 += __shfl_xor_sync(0xffffffffu, sum0, 2);
        sum1 += __shfl_xor_sync(0xffffffffu, sum1, 1);
        sum1 += __shfl_xor_sync(0xffffffffu, sum1, 2);

        l0 = l0 * al0 + sum0;  m0 = mn0;
        l1 = l1 * al1 + sum1;  m1 = mn1;

        #pragma unroll
        for (int nc = 0; nc < 8; ++nc) {
            O[nc][0] *= al0; O[nc][1] *= al0;
            O[nc][2] *= al1; O[nc][3] *= al1;
        }

        #pragma unroll
        for (int nc = 0; nc < 8; ++nc)
            #pragma unroll
            for (int j = 0; j < 4; ++j)
                sacc[nc][j] = __uint_as_float(f2tf32(sacc[nc][j]));

        if (i + 1 < NITER) cp_wait<1>(); else cp_wait<0>();
        __syncthreads();

        // ---- O += P @ V ; P A-fragments via intra-quad shuffles ----
        #pragma unroll
        for (int ks = 0; ks < 8; ++ks) {
            float x0 = __shfl_sync(0xffffffffu, sacc[ks][0], src0);
            float x1 = __shfl_sync(0xffffffffu, sacc[ks][1], src0);
            float x2 = __shfl_sync(0xffffffffu, sacc[ks][2], src0);
            float x3 = __shfl_sync(0xffffffffu, sacc[ks][3], src0);
            float y0 = __shfl_sync(0xffffffffu, sacc[ks][0], src2);
            float y1 = __shfl_sync(0xffffffffu, sacc[ks][1], src2);
            float y2 = __shfl_sync(0xffffffffu, sacc[ks][2], src2);
            float y3 = __shfl_sync(0xffffffffu, sacc[ks][3], src2);
            uint32_t a0 = __float_as_uint(odd ? x1 : x0);
            uint32_t a1 = __float_as_uint(odd ? x3 : x2);
            uint32_t a2 = __float_as_uint(odd ? y1 : y0);
            uint32_t a3 = __float_as_uint(odd ? y3 : y2);
            #pragma unroll
            for (int nc = 0; nc < 8; ++nc) {
                uint32_t b0 = sV[(8 * ks + tig)     * SVP + 8 * nc + gid];
                uint32_t b1 = sV[(8 * ks + tig + 4) * SVP + 8 * nc + gid];
                mma_tf32(O[nc], a0, a1, a2, a3, b0, b1);
            }
        }
        __syncthreads();

        if (i + 1 < NITER) {
            const float* Vg = g_V + ((size_t)b * SEQ + sbeg + (i + 1) * BN) * HD;
            #pragma unroll
            for (int it = 0; it < 8; ++it) {
                int idx = tid + it * 128;
                int r  = idx >> 4;
                int c4 = idx & 15;
                cp_async16(sV_base + (r * SVP + 4 * c4) * 4, &Vg[(size_t)r * HD + 4 * c4]);
            }
            cp_commit();
        }
    }

    // ---- Write unnormalized partials + stats ----
    const size_t row0g = (size_t)b * SEQ + t0;
    float* Op = g_O4 + (size_t)split * BT * HD;
    #pragma unroll
    for (int nc = 0; nc < 8; ++nc) {
        int c = 8 * nc + 2 * tig;
        float* p0 = &Op[(row0g + mrow)     * HD + c];
        float* p1 = &Op[(row0g + mrow + 8) * HD + c];
        *(float2*)p0 = make_float2(O[nc][0], O[nc][1]);
        *(float2*)p1 = make_float2(O[nc][2], O[nc][3]);
    }
    if (tig == 0) {
        g_M4[split * BT + row0g + mrow]     = m0;
        g_M4[split * BT + row0g + mrow + 8] = m1;
        g_L4[split * BT + row0g + mrow]     = l0;
        g_L4[split * BT + row0g + mrow + 8] = l1;
    }
}

// ---------------------------------------------------------------------------
// Combine splits (exp2 domain): O = sum_s w_s O_s / sum_s w_s l_s.
// ---------------------------------------------------------------------------
__global__ __launch_bounds__(256) void combine_kernel(float* __restrict__ out)
{
    int idx = blockIdx.x * 256 + threadIdx.x;
    int row = idx >> 4;

    float m[NSPLIT], l[NSPLIT];
    float mstar = -1e30f;
    #pragma unroll
    for (int s = 0; s < NSPLIT; ++s) {
        m[s] = g_M4[s * BT + row];
        l[s] = g_L4[s * BT + row];
        mstar = fmaxf(mstar, m[s]);
    }
    float den = 0.f;
    float4 num = make_float4(0.f, 0.f, 0.f, 0.f);
    #pragma unroll
    for (int s = 0; s < NSPLIT; ++s) {
        float wgt = ex2(m[s] - mstar);
        den += wgt * l[s];
        float4 o = *(const float4*)&g_O4[(size_t)s * BT * HD + (size_t)idx * 4];
        num.x += wgt * o.x; num.y += wgt * o.y;
        num.z += wgt * o.z; num.w += wgt * o.w;
    }
    float inv = 1.0f / den;
    num.x *= inv; num.y *= inv; num.z *= inv; num.w *= inv;
    *(float4*)&out[(size_t)idx * 4] = num;
}

extern "C" void kernel_launch(void* const* d_in, const int* in_sizes, int n_in,
                              void* d_out, int out_size)
{
    const float* x  = (const float*)d_in[0];
    const float* wq = (const float*)d_in[1];
    const float* wk = (const float*)d_in[2];
    const float* wv = (const float*)d_in[3];
    float* out = (float*)d_out;

    dim3 gridP(BT / 128, 3);
    proj_kernel<<<gridP, 128>>>(x, wq, wk, wv);

    dim3 gridA(SEQ / BM, BATCH, NSPLIT);
    attn_kernel<<<gridA, 128>>>();

    combine_kernel<<<BT * HD / 4 / 256, 256>>>(out);
}